// round 5
// baseline (speedup 1.0000x reference)
#include <cuda_runtime.h>
#include <math.h>

#define BATCH    2048
#define FID      65536
#define CHUNK    1024               // columns per block (256 threads * float4)
#define NCHUNK   (FID / CHUNK)      // 64
#define ROWS_PB  16                 // rows per inner tile
#define NROWG    (BATCH / ROWS_PB)  // 128 row groups
#define GY_SLOTS 16                 // rowgroup slots (grid.y)
#define G_ITERS  (NROWG / GY_SLOTS) // 8 rowgroups per block
#define WARPS_PB 8                  // 256 threads

// Scratch (zero-initialized; counters self-reset each run for graph replay)
__device__ float        g_partials[BATCH * NCHUNK];   // 512 KB
__device__ float        g_lossp[GY_SLOTS];
__device__ unsigned int g_rg_count[GY_SLOTS];
__device__ unsigned int g_final_count;

// ---------------------------------------------------------------------------
// Single kernel. Grid (64, 16) = 1024 blocks.
//  Phase A: stream 8 rowgroups x 16 rows of gate against the register-resident
//           bias chunk, write one partial per (row, chunk).
//  Phase B: last of the 64 chunk-blocks in slot gy finalizes the 128 rows this
//           slot owns (logits, pred, per-slot loss). No spinning -> safe at any
//           residency.
//  Phase C: last of the 16 slot-finalizers sums the slot losses (fixed order).
// out layout: [logits(2048), pred(2048), loss(1)]
// ---------------------------------------------------------------------------
__global__ void __launch_bounds__(256) lr_kernel(
    const float* __restrict__ gate, const float* __restrict__ bias,
    const float* __restrict__ global_bias, const float* __restrict__ label,
    float* __restrict__ out)
{
    const int c    = blockIdx.x;        // column chunk 0..63
    const int gy   = blockIdx.y;        // rowgroup slot 0..15
    const int tid  = threadIdx.x;
    const int warp = tid >> 5;
    const int lane = tid & 31;

    const int col = c * CHUNK + tid * 4;
    const float4 b4 = *reinterpret_cast<const float4*>(bias + col);

    __shared__ float sm[ROWS_PB][WARPS_PB];

    // ---------------- Phase A: streaming dot ---------------------------------
    for (int gi = 0; gi < G_ITERS; ++gi) {
        const int g = gy + gi * GY_SLOTS;   // rowgroup 0..127
        const float* gbase = gate + (size_t)(g * ROWS_PB) * FID + col;

#pragma unroll
        for (int r = 0; r < ROWS_PB; ++r) {
            float4 x = *reinterpret_cast<const float4*>(gbase + (size_t)r * FID);
            float v = x.x * b4.x + x.y * b4.y + x.z * b4.z + x.w * b4.w;
            v += __shfl_xor_sync(0xffffffffu, v, 16);
            v += __shfl_xor_sync(0xffffffffu, v, 8);
            v += __shfl_xor_sync(0xffffffffu, v, 4);
            v += __shfl_xor_sync(0xffffffffu, v, 2);
            v += __shfl_xor_sync(0xffffffffu, v, 1);
            if (lane == 0) sm[r][warp] = v;
        }
        __syncthreads();

        if (tid < ROWS_PB) {
            float t = 0.0f;
#pragma unroll
            for (int w = 0; w < WARPS_PB; ++w) t += sm[tid][w];
            g_partials[(size_t)(g * ROWS_PB + tid) * NCHUNK + c] = t;
        }
        __syncthreads();
    }

    // ---------------- Phase B: per-slot finalize ------------------------------
    __shared__ int s_is_final;
    if (tid == 0) {
        __threadfence();                              // release partials
        unsigned old = atomicAdd(&g_rg_count[gy], 1u);
        s_is_final = (old == NCHUNK - 1);
        if (s_is_final) g_rg_count[gy] = 0;           // reset for graph replay
    }
    __syncthreads();
    if (!s_is_final) return;
    __threadfence();                                  // acquire partials

    const float gb = global_bias[0];
    // warp w owns rowgroup gy + w*16 -> 16 rows
    const int g2 = gy + warp * GY_SLOTS;
    float lloss = 0.0f;                               // valid on lane 0
#pragma unroll
    for (int r = 0; r < ROWS_PB; ++r) {
        const int row = g2 * ROWS_PB + r;
        const float* p = g_partials + (size_t)row * NCHUNK;
        float s = p[lane] + p[lane + 32];
        s += __shfl_xor_sync(0xffffffffu, s, 16);
        s += __shfl_xor_sync(0xffffffffu, s, 8);
        s += __shfl_xor_sync(0xffffffffu, s, 4);
        s += __shfl_xor_sync(0xffffffffu, s, 2);
        s += __shfl_xor_sync(0xffffffffu, s, 1);
        if (lane == 0) {
            float logit = s + gb;
            out[row]         = logit;
            out[BATCH + row] = 1.0f / (1.0f + __expf(-logit));
            float y = label[row];
            lloss += fmaxf(logit, 0.0f) - logit * y + log1pf(expf(-fabsf(logit)));
        }
    }

    __shared__ float slw[WARPS_PB];
    if (lane == 0) slw[warp] = lloss;
    __syncthreads();

    // ---------------- Phase C: global loss -----------------------------------
    __shared__ int s_is_last;
    if (tid == 0) {
        float gl = 0.0f;
#pragma unroll
        for (int w = 0; w < WARPS_PB; ++w) gl += slw[w];   // fixed order
        g_lossp[gy] = gl;
        __threadfence();
        unsigned old = atomicAdd(&g_final_count, 1u);
        s_is_last = (old == GY_SLOTS - 1);
        if (s_is_last) g_final_count = 0;             // reset for graph replay
    }
    __syncthreads();
    if (!s_is_last) return;

    if (tid == 0) {
        __threadfence();
        float total = 0.0f;
#pragma unroll
        for (int i = 0; i < GY_SLOTS; ++i) total += g_lossp[i];  // fixed order
        out[2 * BATCH] = total;
    }
}

// ---------------------------------------------------------------------------
extern "C" void kernel_launch(void* const* d_in, const int* in_sizes, int n_in,
                              void* d_out, int out_size)
{
    const float* gate        = (const float*)d_in[0]; // [2048, 65536]
    const float* sparse_bias = (const float*)d_in[1]; // [65536]
    const float* global_bias = (const float*)d_in[2]; // [1]
    const float* label       = (const float*)d_in[3]; // [2048]
    float* out = (float*)d_out;                       // [4097]

    dim3 grid(NCHUNK, GY_SLOTS);
    lr_kernel<<<grid, 256>>>(gate, sparse_bias, global_bias, label, out);
}

// round 6
// speedup vs baseline: 1.1190x; 1.1190x over previous
#include <cuda_runtime.h>
#include <math.h>

#define BATCH    2048
#define FID      65536
#define CHUNK    1024                // cols per chunk (256 threads * float4)
#define NSPLIT   16                  // column splits (grid.x)
#define COLS_PB  (FID / NSPLIT)      // 4096 cols per block
#define NIT      (COLS_PB / CHUNK)   // 4 chunk iterations per block
#define ROWS_PB  16                  // rows per block
#define NROWG    (BATCH / ROWS_PB)   // 128 row groups (grid.y)
#define WARPS_PB 8                   // 256 threads

// Scratch (zero-initialized; counter self-resets each run for graph replay)
__device__ float        g_partials[BATCH * NSPLIT];   // 128 KB
__device__ float        g_lossp[8];
__device__ unsigned int g_final_count;

// ---------------------------------------------------------------------------
// Kernel 1: streaming dot with thread-local accumulators. Hot loop has NO
// shfl / STS / syncthreads — just LDG.128 + 4 FFMA per row. Block-level
// reduction happens exactly once at the end.
// ---------------------------------------------------------------------------
__global__ void __launch_bounds__(256) dot_partials_kernel(
    const float* __restrict__ gate, const float* __restrict__ bias)
{
    const int cs   = blockIdx.x;        // column split 0..15
    const int g    = blockIdx.y;        // row group 0..127
    const int tid  = threadIdx.x;
    const int warp = tid >> 5;
    const int lane = tid & 31;

    float s[ROWS_PB];
#pragma unroll
    for (int r = 0; r < ROWS_PB; ++r) s[r] = 0.0f;

    const size_t row0 = (size_t)g * ROWS_PB;

    for (int it = 0; it < NIT; ++it) {
        const int col = cs * COLS_PB + it * CHUNK + tid * 4;
        const float4 b4 = *reinterpret_cast<const float4*>(bias + col);
        const float* gbase = gate + row0 * FID + col;

#pragma unroll
        for (int r = 0; r < ROWS_PB; ++r) {
            float4 x = *reinterpret_cast<const float4*>(gbase + (size_t)r * FID);
            s[r] += x.x * b4.x + x.y * b4.y + x.z * b4.z + x.w * b4.w;
        }
    }

    // One block-level reduction: warp shfl per row, then 16 threads sum warps.
    __shared__ float sm[ROWS_PB][WARPS_PB];
#pragma unroll
    for (int r = 0; r < ROWS_PB; ++r) {
        float v = s[r];
        v += __shfl_xor_sync(0xffffffffu, v, 16);
        v += __shfl_xor_sync(0xffffffffu, v, 8);
        v += __shfl_xor_sync(0xffffffffu, v, 4);
        v += __shfl_xor_sync(0xffffffffu, v, 2);
        v += __shfl_xor_sync(0xffffffffu, v, 1);
        if (lane == 0) sm[r][warp] = v;
    }
    __syncthreads();

    if (tid < ROWS_PB) {
        float t = 0.0f;
#pragma unroll
        for (int w = 0; w < WARPS_PB; ++w) t += sm[tid][w];
        g_partials[(row0 + tid) * NSPLIT + cs] = t;
    }
}

// ---------------------------------------------------------------------------
// Kernel 2: epilogue. 8 blocks x 256 threads, one row per thread: sum 16
// partials (fixed order), emit logit/pred, block-reduce loss, last block
// emits total. out layout: [logits(2048), pred(2048), loss(1)]
// ---------------------------------------------------------------------------
__global__ void __launch_bounds__(256) finalize_kernel(
    const float* __restrict__ label, const float* __restrict__ global_bias,
    float* __restrict__ out)
{
    const int tid = threadIdx.x;
    const int row = blockIdx.x * 256 + tid;

    const float4* p = reinterpret_cast<const float4*>(g_partials + (size_t)row * NSPLIT);
    float s = 0.0f;
#pragma unroll
    for (int i = 0; i < NSPLIT / 4; ++i) {
        float4 v = p[i];
        s += v.x + v.y + v.z + v.w;
    }

    float logit = s + global_bias[0];
    out[row]         = logit;
    out[BATCH + row] = 1.0f / (1.0f + __expf(-logit));
    float y = label[row];
    float loss = fmaxf(logit, 0.0f) - logit * y + log1pf(expf(-fabsf(logit)));

    // deterministic block tree reduce of 256 losses
    __shared__ float sl[256];
    sl[tid] = loss;
    __syncthreads();
#pragma unroll
    for (int off = 128; off > 0; off >>= 1) {
        if (tid < off) sl[tid] += sl[tid + off];
        __syncthreads();
    }
    if (tid == 0) g_lossp[blockIdx.x] = sl[0];

    __shared__ int s_is_last;
    if (tid == 0) {
        __threadfence();
        unsigned old = atomicAdd(&g_final_count, 1u);
        s_is_last = (old == 7);
        if (s_is_last) g_final_count = 0;   // reset for next graph replay
    }
    __syncthreads();
    if (!s_is_last) return;

    if (tid == 0) {
        __threadfence();
        float total = 0.0f;
#pragma unroll
        for (int i = 0; i < 8; ++i) total += g_lossp[i];  // fixed order
        out[2 * BATCH] = total;
    }
}

// ---------------------------------------------------------------------------
extern "C" void kernel_launch(void* const* d_in, const int* in_sizes, int n_in,
                              void* d_out, int out_size)
{
    const float* gate        = (const float*)d_in[0]; // [2048, 65536]
    const float* sparse_bias = (const float*)d_in[1]; // [65536]
    const float* global_bias = (const float*)d_in[2]; // [1]
    const float* label       = (const float*)d_in[3]; // [2048]
    float* out = (float*)d_out;                       // [4097]

    dim3 grid1(NSPLIT, NROWG);
    dot_partials_kernel<<<grid1, 256>>>(gate, sparse_bias);
    finalize_kernel<<<8, 256>>>(label, global_bias, out);
}